// round 15
// baseline (speedup 1.0000x reference)
#include <cuda_runtime.h>
#include <cuda_bf16.h>
#include <cuda_fp16.h>
#include <cstdint>
#include <math.h>

#define BB 32
#define LL 512
#define DD 1024
#define HH 16
#define HDIM 64
#define EE 8

// ---------------- scratch (device globals; no allocation allowed) ----------------
__device__ float g_cos[LL * 32];
__device__ float g_sin[LL * 32];
__device__ int   g_routes[BB];

// X/AO tiles (single fp16): [rt(128)][kc(16)] each 128 rows x 64 cols (16KB), SW128
__device__ __half g_xh[(size_t)16384 * 1024];
// W^T tiles (single fp16): [mode(4)][e(8)][nt(8)][kc(16)] each 128(n) x 64(k), SW128
__device__ __half g_wt[(size_t)4 * 8 * 1024 * 1024];
// q/k/v single fp16: [B*H][512][64], SW128-swizzled 128B rows
__device__ __half g_qh[(size_t)BB * HH * LL * HDIM];
__device__ __half g_kh[(size_t)BB * HH * LL * HDIM];
__device__ __half g_vh[(size_t)BB * HH * LL * HDIM];

// ---------------- PTX helpers ----------------
__device__ __forceinline__ uint32_t smem_u32(const void* p) {
    uint32_t a;
    asm("{ .reg .u64 t; cvta.to.shared.u64 t, %1; cvt.u32.u64 %0, t; }" : "=r"(a) : "l"(p));
    return a;
}

#define MBAR_INIT(a, n) \
    asm volatile("mbarrier.init.shared.b64 [%0], %1;" :: "r"(a), "r"((uint32_t)(n)) : "memory")
#define MBAR_EXPECT_TX(a, b) \
    asm volatile("mbarrier.arrive.expect_tx.shared.b64 _, [%0], %1;" :: "r"(a), "r"((uint32_t)(b)) : "memory")
#define MBAR_ARRIVE(a) \
    asm volatile("mbarrier.arrive.shared.b64 _, [%0];" :: "r"(a) : "memory")

__device__ __forceinline__ void mbar_wait(uint32_t mbar, uint32_t parity) {
    asm volatile(
        "{\n\t.reg .pred P;\n\t"
        "WL_%=:\n\t"
        "mbarrier.try_wait.parity.acquire.cta.shared::cta.b64 P, [%0], %1, 0x989680;\n\t"
        "@P bra.uni WD_%=;\n\t"
        "bra.uni WL_%=;\n\t"
        "WD_%=:\n\t}"
        :: "r"(mbar), "r"(parity) : "memory");
}

__device__ __forceinline__ void bulk_g2s(uint32_t dst, const void* src, uint32_t bytes, uint32_t mbar) {
    asm volatile(
        "cp.async.bulk.shared::cluster.global.mbarrier::complete_tx::bytes [%0], [%1], %2, [%3];"
        :: "r"(dst), "l"(src), "r"(bytes), "r"(mbar) : "memory");
}

__device__ __forceinline__ void ldsm_x4(uint32_t* r, uint32_t a) {
    asm volatile("ldmatrix.sync.aligned.m8n8.x4.shared.b16 {%0,%1,%2,%3}, [%4];"
                 : "=r"(r[0]), "=r"(r[1]), "=r"(r[2]), "=r"(r[3]) : "r"(a));
}
__device__ __forceinline__ void ldsm_x4t(uint32_t* r, uint32_t a) {
    asm volatile("ldmatrix.sync.aligned.m8n8.x4.trans.shared.b16 {%0,%1,%2,%3}, [%4];"
                 : "=r"(r[0]), "=r"(r[1]), "=r"(r[2]), "=r"(r[3]) : "r"(a));
}
__device__ __forceinline__ void mma_f16(float* d, const uint32_t* a, const uint32_t* b) {
    asm volatile(
        "mma.sync.aligned.m16n8k16.row.col.f32.f16.f16.f32 "
        "{%0,%1,%2,%3}, {%4,%5,%6,%7}, {%8,%9}, {%0,%1,%2,%3};"
        : "+f"(d[0]), "+f"(d[1]), "+f"(d[2]), "+f"(d[3])
        : "r"(a[0]), "r"(a[1]), "r"(a[2]), "r"(a[3]), "r"(b[0]), "r"(b[1]));
}
__device__ __forceinline__ float ex2(float x) {
    float r;
    asm("ex2.approx.f32 %0, %1;" : "=f"(r) : "f"(x));
    return r;
}

__device__ __forceinline__ uint32_t pack_h2(__half a, __half b) {
    return (uint32_t)__half_as_ushort(a) | ((uint32_t)__half_as_ushort(b) << 16);
}

// ---------------- merged convert: X tiles + W^T tiles + rope + router ----------------
__global__ void convert_kernel(const float* __restrict__ x,
                               const float* __restrict__ qw, const float* __restrict__ kw,
                               const float* __restrict__ vw, const float* __restrict__ ow,
                               const float* __restrict__ rw, const float* __restrict__ rb,
                               float* __restrict__ probs_out, int write_probs) {
    __shared__ float sm[64][129];
    const int bid = blockIdx.x;
    const int tid = threadIdx.x;

    if (bid >= 6152) {
        // ---- router: 32 blocks, one batch each ----
        float* mean = &sm[0][0];          // 1024 floats
        float* logits = &sm[33][0];       // 8 floats
        const int b = bid - 6152;
        for (int d = tid; d < DD; d += blockDim.x) {
            const float* xp = x + (size_t)b * LL * DD + d;
            float s = 0.f;
            #pragma unroll 8
            for (int l = 0; l < LL; l++) s += xp[(size_t)l * DD];
            mean[d] = s * (1.0f / (float)LL);
        }
        __syncthreads();

        int w = tid >> 5;
        int lane = tid & 31;
        if (w < EE) {
            float s = 0.f;
            for (int d = lane; d < DD; d += 32) s += mean[d] * rw[d * EE + w];
            #pragma unroll
            for (int o = 16; o > 0; o >>= 1) s += __shfl_down_sync(0xffffffffu, s, o);
            if (lane == 0) logits[w] = s + rb[w];
        }
        __syncthreads();

        if (tid == 0) {
            float m = logits[0]; int arg = 0;
            #pragma unroll
            for (int e = 1; e < EE; e++) if (logits[e] > m) { m = logits[e]; arg = e; }
            float p[EE], sum = 0.f;
            #pragma unroll
            for (int e = 0; e < EE; e++) { p[e] = expf(logits[e] - m); sum += p[e]; }
            if (write_probs) {
                float inv = 1.0f / sum;
                #pragma unroll
                for (int e = 0; e < EE; e++) probs_out[b * EE + e] = p[e] * inv;
            }
            g_routes[b] = arg;
        }
        return;
    }

    if (bid >= 6144) {
        // ---- rope tables: 8 blocks ----
        int base = (bid - 6144) * 2048 + tid * 8;
        #pragma unroll
        for (int j = 0; j < 8; j++) {
            int idx = base + j;
            int l = idx >> 5;
            int jp = idx & 31;
            float inv = 1.0f / powf(10000.0f, (float)(2 * jp) / 64.0f);
            float ang = (float)l * inv;
            g_cos[idx] = cosf(ang);
            g_sin[idx] = sinf(ang);
        }
        return;
    }

    if (bid < 2048) {
        const int rt = bid >> 4, kc = bid & 15;
        const size_t tb = ((size_t)rt * 16 + kc) * 8192;
        char* dh = (char*)(g_xh + tb);
        #pragma unroll
        for (int i = 0; i < 4; i++) {
            int u = tid + i * 256;
            int r = u >> 3, k8 = u & 7;
            const float* p = x + ((size_t)(rt * 128 + r)) * DD + kc * 64 + k8 * 8;
            float4 a = *(const float4*)p;
            float4 b4 = *(const float4*)(p + 4);
            uint32_t off = (uint32_t)(u * 16);
            off ^= (off >> 3) & 0x70;
            *(uint4*)(dh + off) = make_uint4(
                pack_h2(__float2half_rn(a.x),  __float2half_rn(a.y)),
                pack_h2(__float2half_rn(a.z),  __float2half_rn(a.w)),
                pack_h2(__float2half_rn(b4.x), __float2half_rn(b4.y)),
                pack_h2(__float2half_rn(b4.z), __float2half_rn(b4.w)));
        }
    } else {
        const int idx = bid - 2048;
        const int kc = idx & 15, nt = (idx >> 4) & 7;
        const int e = (idx >> 7) & 7, mode = idx >> 10;
        const float* W = (mode == 0) ? qw : (mode == 1) ? kw : (mode == 2) ? vw : ow;
        const float* src = W + ((size_t)e * DD + kc * 64) * DD + nt * 128;

        #pragma unroll
        for (int i = 0; i < 8; i++) {
            int idx2 = tid + i * 256;
            int kr = idx2 >> 5, nc = (idx2 & 31) << 2;
            float4 v = *(const float4*)(src + (size_t)kr * DD + nc);
            sm[kr][nc] = v.x; sm[kr][nc + 1] = v.y; sm[kr][nc + 2] = v.z; sm[kr][nc + 3] = v.w;
        }
        __syncthreads();

        const size_t tb = (((size_t)(mode * 8 + e) * 8 + nt) * 16 + kc) * 8192;
        char* dw = (char*)(g_wt + tb);
        #pragma unroll
        for (int i = 0; i < 4; i++) {
            int u = tid + i * 256;
            int n = u >> 3, k8 = u & 7;
            __half h[8];
            #pragma unroll
            for (int j = 0; j < 8; j++) h[j] = __float2half_rn(sm[k8 * 8 + j][n]);
            uint32_t off = (uint32_t)(u * 16);
            off ^= (off >> 3) & 0x70;
            *(uint4*)(dw + off) = make_uint4(pack_h2(h[0], h[1]), pack_h2(h[2], h[3]),
                                             pack_h2(h[4], h[5]), pack_h2(h[6], h[7]));
        }
    }
}

// ---------------- HMMA GEMM: CTA 128x128, warp 64x32, 2 CTAs/SM, 3-stage -------------
__global__ void __launch_bounds__(256, 2) hmma_gemm_kernel(float* __restrict__ out, int mode0) {
    extern __shared__ __align__(1024) char smem[];
    const uint32_t sb = smem_u32(smem);
    const int tid = threadIdx.x;
    const int lane = tid & 31, wid = tid >> 5;
    const int wm = wid >> 2, wn = wid & 3;            // 2(m) x 4(n)
    const int nt = blockIdx.x & 7;
    const int mode = mode0 + (blockIdx.x >> 3);
    const int mt = blockIdx.y, b = blockIdx.z;
    const int e = g_routes[b];

    const uint32_t FULLB = sb;                        // 3 full mbarriers
    const uint32_t EMPTB = sb + 24;                   // 3 empty mbarriers (count 8)
    const uint32_t TILES = sb + 1024;                 // 3 stages x 32KB: A | B

    if (tid == 0) {
        #pragma unroll
        for (int s = 0; s < 3; s++) { MBAR_INIT(FULLB + s * 8, 1); MBAR_INIT(EMPTB + s * 8, 8); }
    }
    __syncthreads();

    const __half* Ah = g_xh + ((size_t)(b * 4 + mt) * 16) * 8192;
    const __half* B0 = g_wt + (((size_t)(mode * 8 + e) * 8 + nt) * 16) * 8192;

    auto issue = [&](int c) {
        int s = c % 3;
        uint32_t fb = FULLB + s * 8;
        uint32_t st = TILES + s * 32768;
        MBAR_EXPECT_TX(fb, 32768);
        bulk_g2s(st,         Ah + (size_t)c * 8192, 16384, fb);
        bulk_g2s(st + 16384, B0 + (size_t)c * 8192, 16384, fb);
    };
    if (tid == 0) { issue(0); issue(1); issue(2); }

    float acc[4][4][4];
    #pragma unroll
    for (int mf = 0; mf < 4; mf++)
        #pragma unroll
        for (int nf = 0; nf < 4; nf++)
            #pragma unroll
            for (int r = 0; r < 4; r++) acc[mf][nf][r] = 0.f;

    const uint32_t a_row  = (uint32_t)(wm * 64 + (lane & 15)) * 128;
    const uint32_t a_koff = (uint32_t)(lane >> 4) * 16;
    const uint32_t b_row  = (uint32_t)(wn * 32 + (lane & 7) + ((lane >> 4) << 3)) * 128;
    const uint32_t b_koff = (uint32_t)((lane >> 3) & 1) * 16;

    for (int c = 0; c < 16; c++) {
        const int s = c % 3;
        const uint32_t phase = (uint32_t)((c / 3) & 1);
        mbar_wait(FULLB + s * 8, phase);
        const uint32_t base = TILES + s * 32768;

        #pragma unroll
        for (int ks = 0; ks < 4; ks++) {
            const uint32_t k0b = (uint32_t)ks * 32;
            uint32_t ah[4][4];
            #pragma unroll
            for (int mf = 0; mf < 4; mf++) {
                uint32_t byt = a_row + (uint32_t)mf * 2048 + a_koff + k0b;
                uint32_t sw = byt ^ ((byt >> 3) & 0x70);
                ldsm_x4(ah[mf], base + sw);
            }
            uint32_t bf[2][4];
            #pragma unroll
            for (int p = 0; p < 2; p++) {
                uint32_t byt = b_row + (uint32_t)p * 2048 + b_koff + k0b;
                uint32_t sw = byt ^ ((byt >> 3) & 0x70);
                ldsm_x4(bf[p], base + 16384 + sw);
            }
            if (ks == 3 && lane == 0) MBAR_ARRIVE(EMPTB + s * 8);

            #pragma unroll
            for (int p = 0; p < 2; p++)
                #pragma unroll
                for (int mf = 0; mf < 4; mf++) {
                    mma_f16(acc[mf][2 * p],     ah[mf], &bf[p][0]);
                    mma_f16(acc[mf][2 * p + 1], ah[mf], &bf[p][2]);
                }
        }
        if (tid == 0 && c + 3 < 16) {
            mbar_wait(EMPTB + s * 8, phase);
            issue(c + 3);
        }
    }

    // ---------------- epilogue ----------------
    const int l_base = mt * 128 + wm * 64 + (lane >> 2);
    const int tig = lane & 3;
    const int colbase = nt * 128 + wn * 32;
    const int hglob = colbase >> 6;
    const int d0 = colbase & 63;

    #pragma unroll
    for (int mf = 0; mf < 4; mf++) {
        #pragma unroll
        for (int rh = 0; rh < 2; rh++) {
            const int l = l_base + mf * 16 + 8 * rh;
            #pragma unroll
            for (int nf = 0; nf < 4; nf++) {
                const int d = d0 + 8 * nf + 2 * tig;
                float x0 = acc[mf][nf][2 * rh];
                float x1 = acc[mf][nf][2 * rh + 1];
                if (mode == 3) {
                    float2* dst = (float2*)(out + ((size_t)b * LL + l) * DD + hglob * 64 + d);
                    *dst = make_float2(x0, x1);
                } else {
                    float y0, y1;
                    if (mode == 2) { y0 = x0; y1 = x1; }
                    else {
                        const int p = d >> 1;
                        float cs = g_cos[l * 32 + p];
                        float sn = g_sin[l * 32 + p];
                        y0 = x0 * cs - x1 * sn;
                        y1 = x1 * cs + x0 * sn;
                    }
                    uint32_t off = (uint32_t)((((b * HH + hglob) * LL) + l) * 128 + d * 2);
                    uint32_t sw = off ^ ((off >> 3) & 0x70);
                    char* dst = (mode == 0) ? (char*)g_qh : (mode == 1) ? (char*)g_kh : (char*)g_vh;
                    *(uint32_t*)(dst + sw) = pack_h2(__float2half_rn(y0), __float2half_rn(y1));
                }
            }
        }
    }
}

// ---------------- flash attention: paired q-tiles, mbarrier-only sync ----------------
__global__ void __launch_bounds__(256, 2) attn_kernel() {
    extern __shared__ __align__(1024) char smem[];
    const uint32_t sb = smem_u32(smem);
    const int tid = threadIdx.x, lane = tid & 31, w = tid >> 5;
    const int bx = blockIdx.x;           // 0 or 1
    const int qtA = 3 - bx, qtB = bx;
    const int bh = blockIdx.y;
    const int b = bh >> 4, h = bh & 15;
    const int g = lane >> 2, tig = lane & 3;
    const float S2 = 0.125f * 1.44269504088896341f;

    const uint32_t QB = sb;
    const uint32_t FB = sb + 8;                    // 2 full mbarriers
    const uint32_t EB = sb + 24;                   // 2 empty mbarriers (count 8)
    const uint32_t QT = sb + 1024;                 // 2 Q tiles x 16KB
    const uint32_t KV = sb + 1024 + 32768;         // 2 stages x (Kh 8KB | Vh 8KB)

    if (tid == 0) {
        MBAR_INIT(QB, 1);
        MBAR_INIT(FB, 1); MBAR_INIT(FB + 8, 1);
        MBAR_INIT(EB, 8); MBAR_INIT(EB + 8, 8);
    }
    __syncthreads();

    const size_t bh_off = (size_t)bh * LL * HDIM;
    const __half* kh = g_kh + bh_off;
    const __half* vh = g_vh + bh_off;

    const int n1 = 2 * qtA + 2, n2 = 2 * qtB + 2;
    const int ntot = n1 + n2;            // always 10

    auto issue = [&](int i) {
        int jt = (i < n1) ? i : (i - n1);
        int s = i & 1;
        uint32_t fb = FB + s * 8;
        uint32_t st = KV + s * 16384;
        MBAR_EXPECT_TX(fb, 16384);
        bulk_g2s(st,        kh + (size_t)jt * 4096, 8192, fb);
        bulk_g2s(st + 8192, vh + (size_t)jt * 4096, 8192, fb);
    };
    if (tid == 0) {
        MBAR_EXPECT_TX(QB, 32768);
        bulk_g2s(QT,         g_qh + bh_off + (size_t)qtA * 8192, 16384, QB);
        bulk_g2s(QT + 16384, g_qh + bh_off + (size_t)qtB * 8192, 16384, QB);
        issue(0);
        issue(1);
    }

    // precomputed swizzled Q ldmatrix offsets (ks-major); swizzle field is ks-invariant
    uint32_t swq[4];
    {
        uint32_t q0 = (uint32_t)(w * 16 + (lane & 15)) * 128 + (uint32_t)(lane >> 4) * 16;
        #pragma unroll
        for (int ks = 0; ks < 4; ks++) {
            uint32_t byt = q0 + (uint32_t)ks * 32;
            swq[ks] = byt ^ ((byt >> 3) & 0x70);
        }
    }

    float o[8][4];
    #pragma unroll
    for (int nf = 0; nf < 8; nf++)
        #pragma unroll
        for (int r = 0; r < 4; r++) o[nf][r] = 0.f;
    float m0 = -1e30f, m1 = -1e30f, l0 = 0.f, l1 = 0.f;

    mbar_wait(QB, 0);

    for (int i = 0; i < ntot; i++) {
        const int pass = (i >= n1);
        const int jt = pass ? (i - n1) : i;
        const int qt = pass ? qtB : qtA;
        const uint32_t qtile = QT + (pass ? 16384u : 0u);
        const int rowmin = qt * 128 + w * 16;

        const int s = i & 1;
        mbar_wait(FB + s * 8, (uint32_t)((i >> 1) & 1));
        const uint32_t kb = KV + s * 16384;

        if (jt * 64 <= rowmin + 15) {
            float p[8][4];
            #pragma unroll
            for (int nf = 0; nf < 8; nf++)
                #pragma unroll
                for (int r = 0; r < 4; r++) p[nf][r] = 0.f;

            // S = Q K^T
            #pragma unroll
            for (int ks = 0; ks < 4; ks++) {
                uint32_t ah[4];
                ldsm_x4(ah, qtile + swq[ks]);
                #pragma unroll
                for (int nfp = 0; nfp < 4; nfp++) {
                    uint32_t koff = (uint32_t)(nfp * 16 + (lane & 7) + ((lane & 16) >> 1)) * 128
                                    + (uint32_t)ks * 32 + ((lane & 8) << 1);
                    uint32_t swk = koff ^ ((koff >> 3) & 0x70);
                    uint32_t kf[4];
                    ldsm_x4(kf, kb + swk);
                    mma_f16(p[2 * nfp],     ah, &kf[0]);
                    mma_f16(p[2 * nfp + 1], ah, &kf[2]);
                }
            }

            // scale into log2 domain + causal mask
            const bool need_mask = (jt * 64 + 63) > rowmin;
            #pragma unroll
            for (int nf = 0; nf < 8; nf++)
                #pragma unroll
                for (int r = 0; r < 4; r++) {
                    float v = p[nf][r] * S2;
                    if (need_mask) {
                        int qr = rowmin + g + ((r & 2) << 2);
                        int kc = jt * 64 + 8 * nf + 2 * tig + (r & 1);
                        if (kc > qr) v = -1e30f;
                    }
                    p[nf][r] = v;
                }

            float mx0 = m0, mx1 = m1;
            #pragma unroll
            for (int nf = 0; nf < 8; nf++) {
                mx0 = fmaxf(mx0, fmaxf(p[nf][0], p[nf][1]));
                mx1 = fmaxf(mx1, fmaxf(p[nf][2], p[nf][3]));
            }
            mx0 = fmaxf(mx0, __shfl_xor_sync(0xffffffffu, mx0, 1));
            mx0 = fmaxf(mx0, __shfl_xor_sync(0xffffffffu, mx0, 2));
            mx1 = fmaxf(mx1, __shfl_xor_sync(0xffffffffu, mx1, 1));
            mx1 = fmaxf(mx1, __shfl_xor_sync(0xffffffffu, mx1, 2));
            float c0 = ex2(m0 - mx0), c1 = ex2(m1 - mx1);
            m0 = mx0; m1 = mx1;
            float s0 = 0.f, s1 = 0.f;
            #pragma unroll
            for (int nf = 0; nf < 8; nf++) {
                p[nf][0] = ex2(p[nf][0] - mx0); s0 += p[nf][0];
                p[nf][1] = ex2(p[nf][1] - mx0); s0 += p[nf][1];
                p[nf][2] = ex2(p[nf][2] - mx1); s1 += p[nf][2];
                p[nf][3] = ex2(p[nf][3] - mx1); s1 += p[nf][3];
            }
            s0 += __shfl_xor_sync(0xffffffffu, s0, 1);
            s0 += __shfl_xor_sync(0xffffffffu, s0, 2);
            s1 += __shfl_xor_sync(0xffffffffu, s1, 1);
            s1 += __shfl_xor_sync(0xffffffffu, s1, 2);
            l0 = l0 * c0 + s0;
            l1 = l1 * c1 + s1;
            #pragma unroll
            for (int nf = 0; nf < 8; nf++) {
                o[nf][0] *= c0; o[nf][1] *= c0;
                o[nf][2] *= c1; o[nf][3] *= c1;
            }

            // O += P V
            #pragma unroll
            for (int j = 0; j < 4; j++) {
                uint32_t pah[4];
                #pragma unroll
                for (int half = 0; half < 2; half++) {
                    const float* pf = p[2 * j + half];
                    pah[2 * half]     = pack_h2(__float2half_rn(pf[0]), __float2half_rn(pf[1]));
                    pah[2 * half + 1] = pack_h2(__float2half_rn(pf[2]), __float2half_rn(pf[3]));
                }
                #pragma unroll
                for (int nfp = 0; nfp < 4; nfp++) {
                    uint32_t voff = (uint32_t)(16 * j + (lane & 7) + (lane & 8)) * 128
                                    + (uint32_t)nfp * 32 + (lane & 16);
                    uint32_t swv = voff ^ ((voff >> 3) & 0x70);
                    uint32_t vf[4];
                    ldsm_x4t(vf, kb + 8192 + swv);
                    mma_f16(o[2 * nfp],     pah, &vf[0]);
                    mma_f16(o[2 * nfp + 1], pah, &vf[2]);
                }
            }
        }
        // release this stage (all warps, even masked-skip ones)
        if (lane == 0) MBAR_ARRIVE(EB + s * 8);
        if (tid == 0 && i + 2 < ntot) {
            mbar_wait(EB + s * 8, (uint32_t)((i >> 1) & 1));
            issue(i + 2);
        }

        // pass boundary or end: epilogue for this q-tile, then reset state
        if (i == n1 - 1 || i == ntot - 1) {
            const float i0 = 1.f / l0, i1 = 1.f / l1;
            const size_t tb = (((size_t)(b * 4 + qt) * 16) + h) * 16384;   // bytes
            char* dh = (char*)g_xh + tb;
            #pragma unroll
            for (int nf = 0; nf < 8; nf++) {
                #pragma unroll
                for (int rh = 0; rh < 2; rh++) {
                    float y0 = o[nf][2 * rh]     * (rh ? i1 : i0);
                    float y1 = o[nf][2 * rh + 1] * (rh ? i1 : i0);
                    uint32_t off = (uint32_t)((w * 16 + g + 8 * rh) * 128 + (8 * nf + 2 * tig) * 2);
                    uint32_t sw = off ^ ((off >> 3) & 0x70);
                    *(uint32_t*)(dh + sw) = pack_h2(__float2half_rn(y0), __float2half_rn(y1));
                }
            }
            if (i == n1 - 1) {
                #pragma unroll
                for (int nf = 0; nf < 8; nf++)
                    #pragma unroll
                    for (int r = 0; r < 4; r++) o[nf][r] = 0.f;
                m0 = -1e30f; m1 = -1e30f; l0 = 0.f; l1 = 0.f;
            }
        }
    }
}

// ---------------- launch ----------------
extern "C" void kernel_launch(void* const* d_in, const int* in_sizes, int n_in,
                              void* d_out, int out_size) {
    const float* x  = (const float*)d_in[0];
    const float* qw = (const float*)d_in[1];
    const float* kw = (const float*)d_in[2];
    const float* vw = (const float*)d_in[3];
    const float* ow = (const float*)d_in[4];
    const float* rw = (const float*)d_in[5];
    const float* rb = (const float*)d_in[6];
    float* out = (float*)d_out;

    const int GEMM_SMEM = 1024 + 3 * 32768;           // 99328 (x2 CTAs = 198656)
    cudaFuncSetAttribute(hmma_gemm_kernel, cudaFuncAttributeMaxDynamicSharedMemorySize, GEMM_SMEM);
    const int ATTN_SMEM = 1024 + 32768 + 2 * 16384;   // 66560 (x2 CTAs = 133120)
    cudaFuncSetAttribute(attn_kernel, cudaFuncAttributeMaxDynamicSharedMemorySize, ATTN_SMEM);

    int write_probs = (out_size >= BB * LL * DD + BB * EE) ? 1 : 0;

    // convert (X, W, rope) + router merged: 6184 blocks                      // 0
    convert_kernel<<<6184, 256>>>(x, qw, kw, vw, ow, rw, rb,
                                  out + (size_t)BB * LL * DD, write_probs);

    hmma_gemm_kernel<<<dim3(24, 4, BB), 256, GEMM_SMEM>>>(nullptr, 0);        // 1

    attn_kernel<<<dim3(2, BB * HH), 256, ATTN_SMEM>>>();                      // 2 <- profiled

    hmma_gemm_kernel<<<dim3(8, 4, BB), 256, GEMM_SMEM>>>(out, 3);             // 3
}

// round 16
// speedup vs baseline: 1.0146x; 1.0146x over previous
#include <cuda_runtime.h>
#include <cuda_bf16.h>
#include <cuda_fp16.h>
#include <cstdint>
#include <math.h>

#define BB 32
#define LL 512
#define DD 1024
#define HH 16
#define HDIM 64
#define EE 8

// ---------------- scratch (device globals; no allocation allowed) ----------------
__device__ float g_cos[LL * 32];
__device__ float g_sin[LL * 32];
__device__ int   g_routes[BB];
__device__ int   g_done;

// X/AO tiles (single fp16): [rt(128)][kc(16)] each 128 rows x 64 cols (16KB), SW128
__device__ __half g_xh[(size_t)16384 * 1024];
// W^T tiles (single fp16): [mode(4)][e(8)][nt(8)][kc(16)] each 128(n) x 64(k), SW128
__device__ __half g_wt[(size_t)4 * 8 * 1024 * 1024];
// q/k/v single fp16: [B*H][512][64], SW128-swizzled 128B rows
__device__ __half g_qh[(size_t)BB * HH * LL * HDIM];
__device__ __half g_kh[(size_t)BB * HH * LL * HDIM];
__device__ __half g_vh[(size_t)BB * HH * LL * HDIM];

// ---------------- PTX helpers ----------------
__device__ __forceinline__ uint32_t smem_u32(const void* p) {
    uint32_t a;
    asm("{ .reg .u64 t; cvta.to.shared.u64 t, %1; cvt.u32.u64 %0, t; }" : "=r"(a) : "l"(p));
    return a;
}

#define MBAR_INIT(a, n) \
    asm volatile("mbarrier.init.shared.b64 [%0], %1;" :: "r"(a), "r"((uint32_t)(n)) : "memory")
#define MBAR_EXPECT_TX(a, b) \
    asm volatile("mbarrier.arrive.expect_tx.shared.b64 _, [%0], %1;" :: "r"(a), "r"((uint32_t)(b)) : "memory")
#define MBAR_ARRIVE(a) \
    asm volatile("mbarrier.arrive.shared.b64 _, [%0];" :: "r"(a) : "memory")

__device__ __forceinline__ void mbar_wait(uint32_t mbar, uint32_t parity) {
    asm volatile(
        "{\n\t.reg .pred P;\n\t"
        "WL_%=:\n\t"
        "mbarrier.try_wait.parity.acquire.cta.shared::cta.b64 P, [%0], %1, 0x989680;\n\t"
        "@P bra.uni WD_%=;\n\t"
        "bra.uni WL_%=;\n\t"
        "WD_%=:\n\t}"
        :: "r"(mbar), "r"(parity) : "memory");
}

__device__ __forceinline__ void bulk_g2s(uint32_t dst, const void* src, uint32_t bytes, uint32_t mbar) {
    asm volatile(
        "cp.async.bulk.shared::cluster.global.mbarrier::complete_tx::bytes [%0], [%1], %2, [%3];"
        :: "r"(dst), "l"(src), "r"(bytes), "r"(mbar) : "memory");
}

__device__ __forceinline__ void ldsm_x4(uint32_t* r, uint32_t a) {
    asm volatile("ldmatrix.sync.aligned.m8n8.x4.shared.b16 {%0,%1,%2,%3}, [%4];"
                 : "=r"(r[0]), "=r"(r[1]), "=r"(r[2]), "=r"(r[3]) : "r"(a));
}
__device__ __forceinline__ void ldsm_x4t(uint32_t* r, uint32_t a) {
    asm volatile("ldmatrix.sync.aligned.m8n8.x4.trans.shared.b16 {%0,%1,%2,%3}, [%4];"
                 : "=r"(r[0]), "=r"(r[1]), "=r"(r[2]), "=r"(r[3]) : "r"(a));
}
__device__ __forceinline__ void mma_f16(float* d, const uint32_t* a, const uint32_t* b) {
    asm volatile(
        "mma.sync.aligned.m16n8k16.row.col.f32.f16.f16.f32 "
        "{%0,%1,%2,%3}, {%4,%5,%6,%7}, {%8,%9}, {%0,%1,%2,%3};"
        : "+f"(d[0]), "+f"(d[1]), "+f"(d[2]), "+f"(d[3])
        : "r"(a[0]), "r"(a[1]), "r"(a[2]), "r"(a[3]), "r"(b[0]), "r"(b[1]));
}
__device__ __forceinline__ float ex2(float x) {
    float r;
    asm("ex2.approx.f32 %0, %1;" : "=f"(r) : "f"(x));
    return r;
}

__device__ __forceinline__ uint32_t pack_h2(__half a, __half b) {
    return (uint32_t)__half_as_ushort(a) | ((uint32_t)__half_as_ushort(b) << 16);
}

// ---------------- merged convert: router + rope + X tiles + W^T tiles ----------------
__global__ void convert_kernel(const float* __restrict__ x,
                               const float* __restrict__ qw, const float* __restrict__ kw,
                               const float* __restrict__ vw, const float* __restrict__ ow,
                               const float* __restrict__ rw, const float* __restrict__ rb,
                               float* __restrict__ probs_out, int write_probs) {
    __shared__ float sm[64][129];
    const int bid = blockIdx.x;
    const int tid = threadIdx.x;

    if (bid < 32) {
        // ---- router: first so it overlaps the memory wave ----
        float* mean = &sm[0][0];
        float* logits = &sm[33][0];
        const int b = bid;
        for (int d = tid; d < DD; d += blockDim.x) {
            const float* xp = x + (size_t)b * LL * DD + d;
            float s = 0.f;
            #pragma unroll 8
            for (int l = 0; l < LL; l++) s += xp[(size_t)l * DD];
            mean[d] = s * (1.0f / (float)LL);
        }
        __syncthreads();

        int w = tid >> 5;
        int lane = tid & 31;
        if (w < EE) {
            float s = 0.f;
            for (int d = lane; d < DD; d += 32) s += mean[d] * rw[d * EE + w];
            #pragma unroll
            for (int o = 16; o > 0; o >>= 1) s += __shfl_down_sync(0xffffffffu, s, o);
            if (lane == 0) logits[w] = s + rb[w];
        }
        __syncthreads();

        if (tid == 0) {
            float m = logits[0]; int arg = 0;
            #pragma unroll
            for (int e = 1; e < EE; e++) if (logits[e] > m) { m = logits[e]; arg = e; }
            float p[EE], sum = 0.f;
            #pragma unroll
            for (int e = 0; e < EE; e++) { p[e] = expf(logits[e] - m); sum += p[e]; }
            if (write_probs) {
                float inv = 1.0f / sum;
                #pragma unroll
                for (int e = 0; e < EE; e++) probs_out[b * EE + e] = p[e] * inv;
            }
            g_routes[b] = arg;
        }
        return;
    }

    if (bid < 40) {
        // ---- rope tables (+ dependency counter reset) ----
        if (bid == 32 && tid == 0) g_done = 0;
        int base = (bid - 32) * 2048 + tid * 8;
        #pragma unroll
        for (int j = 0; j < 8; j++) {
            int idx = base + j;
            int l = idx >> 5;
            int jp = idx & 31;
            float inv = 1.0f / powf(10000.0f, (float)(2 * jp) / 64.0f);
            float ang = (float)l * inv;
            g_cos[idx] = cosf(ang);
            g_sin[idx] = sinf(ang);
        }
        return;
    }

    if (bid < 2088) {
        const int bx = bid - 40;
        const int rt = bx >> 4, kc = bx & 15;
        const size_t tb = ((size_t)rt * 16 + kc) * 8192;
        char* dh = (char*)(g_xh + tb);
        #pragma unroll
        for (int i = 0; i < 4; i++) {
            int u = tid + i * 256;
            int r = u >> 3, k8 = u & 7;
            const float* p = x + ((size_t)(rt * 128 + r)) * DD + kc * 64 + k8 * 8;
            float4 a = *(const float4*)p;
            float4 b4 = *(const float4*)(p + 4);
            uint32_t off = (uint32_t)(u * 16);
            off ^= (off >> 3) & 0x70;
            *(uint4*)(dh + off) = make_uint4(
                pack_h2(__float2half_rn(a.x),  __float2half_rn(a.y)),
                pack_h2(__float2half_rn(a.z),  __float2half_rn(a.w)),
                pack_h2(__float2half_rn(b4.x), __float2half_rn(b4.y)),
                pack_h2(__float2half_rn(b4.z), __float2half_rn(b4.w)));
        }
    } else {
        const int idx = bid - 2088;
        const int kc = idx & 15, nt = (idx >> 4) & 7;
        const int e = (idx >> 7) & 7, mode = idx >> 10;
        const float* W = (mode == 0) ? qw : (mode == 1) ? kw : (mode == 2) ? vw : ow;
        const float* src = W + ((size_t)e * DD + kc * 64) * DD + nt * 128;

        #pragma unroll
        for (int i = 0; i < 8; i++) {
            int idx2 = tid + i * 256;
            int kr = idx2 >> 5, nc = (idx2 & 31) << 2;
            float4 v = *(const float4*)(src + (size_t)kr * DD + nc);
            sm[kr][nc] = v.x; sm[kr][nc + 1] = v.y; sm[kr][nc + 2] = v.z; sm[kr][nc + 3] = v.w;
        }
        __syncthreads();

        const size_t tb = (((size_t)(mode * 8 + e) * 8 + nt) * 16 + kc) * 8192;
        char* dw = (char*)(g_wt + tb);
        #pragma unroll
        for (int i = 0; i < 4; i++) {
            int u = tid + i * 256;
            int n = u >> 3, k8 = u & 7;
            __half h[8];
            #pragma unroll
            for (int j = 0; j < 8; j++) h[j] = __float2half_rn(sm[k8 * 8 + j][n]);
            uint32_t off = (uint32_t)(u * 16);
            off ^= (off >> 3) & 0x70;
            *(uint4*)(dw + off) = make_uint4(pack_h2(h[0], h[1]), pack_h2(h[2], h[3]),
                                             pack_h2(h[4], h[5]), pack_h2(h[6], h[7]));
        }
    }
}

// ---------------- GEMM body (CTA 128x128, warp 64x32, 3-stage pipeline) --------------
__device__ __forceinline__ void gemm_body(uint32_t sb, int nt, int mode, int mt, int b,
                                          float* __restrict__ out) {
    const int tid = threadIdx.x;
    const int lane = tid & 31, wid = tid >> 5;
    const int wm = wid >> 2, wn = wid & 3;
    const int e = g_routes[b];

    const uint32_t FULLB = sb;
    const uint32_t EMPTB = sb + 24;
    const uint32_t TILES = sb + 1024;

    if (tid == 0) {
        #pragma unroll
        for (int s = 0; s < 3; s++) { MBAR_INIT(FULLB + s * 8, 1); MBAR_INIT(EMPTB + s * 8, 8); }
    }
    __syncthreads();

    const __half* Ah = g_xh + ((size_t)(b * 4 + mt) * 16) * 8192;
    const __half* B0 = g_wt + (((size_t)(mode * 8 + e) * 8 + nt) * 16) * 8192;

    auto issue = [&](int c) {
        int s = c % 3;
        uint32_t fb = FULLB + s * 8;
        uint32_t st = TILES + s * 32768;
        MBAR_EXPECT_TX(fb, 32768);
        bulk_g2s(st,         Ah + (size_t)c * 8192, 16384, fb);
        bulk_g2s(st + 16384, B0 + (size_t)c * 8192, 16384, fb);
    };
    if (tid == 0) { issue(0); issue(1); issue(2); }

    float acc[4][4][4];
    #pragma unroll
    for (int mf = 0; mf < 4; mf++)
        #pragma unroll
        for (int nf = 0; nf < 4; nf++)
            #pragma unroll
            for (int r = 0; r < 4; r++) acc[mf][nf][r] = 0.f;

    const uint32_t a_row  = (uint32_t)(wm * 64 + (lane & 15)) * 128;
    const uint32_t a_koff = (uint32_t)(lane >> 4) * 16;
    const uint32_t b_row  = (uint32_t)(wn * 32 + (lane & 7) + ((lane >> 4) << 3)) * 128;
    const uint32_t b_koff = (uint32_t)((lane >> 3) & 1) * 16;

    for (int c = 0; c < 16; c++) {
        const int s = c % 3;
        const uint32_t phase = (uint32_t)((c / 3) & 1);
        mbar_wait(FULLB + s * 8, phase);
        const uint32_t base = TILES + s * 32768;

        #pragma unroll
        for (int ks = 0; ks < 4; ks++) {
            const uint32_t k0b = (uint32_t)ks * 32;
            uint32_t ah[4][4];
            #pragma unroll
            for (int mf = 0; mf < 4; mf++) {
                uint32_t byt = a_row + (uint32_t)mf * 2048 + a_koff + k0b;
                uint32_t sw = byt ^ ((byt >> 3) & 0x70);
                ldsm_x4(ah[mf], base + sw);
            }
            uint32_t bf[2][4];
            #pragma unroll
            for (int p = 0; p < 2; p++) {
                uint32_t byt = b_row + (uint32_t)p * 2048 + b_koff + k0b;
                uint32_t sw = byt ^ ((byt >> 3) & 0x70);
                ldsm_x4(bf[p], base + 16384 + sw);
            }
            if (ks == 3 && lane == 0) MBAR_ARRIVE(EMPTB + s * 8);

            #pragma unroll
            for (int p = 0; p < 2; p++)
                #pragma unroll
                for (int mf = 0; mf < 4; mf++) {
                    mma_f16(acc[mf][2 * p],     ah[mf], &bf[p][0]);
                    mma_f16(acc[mf][2 * p + 1], ah[mf], &bf[p][2]);
                }
        }
        if (tid == 0 && c + 3 < 16) {
            mbar_wait(EMPTB + s * 8, phase);
            issue(c + 3);
        }
    }

    const int l_base = mt * 128 + wm * 64 + (lane >> 2);
    const int tig = lane & 3;
    const int colbase = nt * 128 + wn * 32;
    const int hglob = colbase >> 6;
    const int d0 = colbase & 63;

    #pragma unroll
    for (int mf = 0; mf < 4; mf++) {
        #pragma unroll
        for (int rh = 0; rh < 2; rh++) {
            const int l = l_base + mf * 16 + 8 * rh;
            #pragma unroll
            for (int nf = 0; nf < 4; nf++) {
                const int d = d0 + 8 * nf + 2 * tig;
                float x0 = acc[mf][nf][2 * rh];
                float x1 = acc[mf][nf][2 * rh + 1];
                if (mode == 3) {
                    float2* dst = (float2*)(out + ((size_t)b * LL + l) * DD + hglob * 64 + d);
                    *dst = make_float2(x0, x1);
                } else {
                    float y0, y1;
                    if (mode == 2) { y0 = x0; y1 = x1; }
                    else {
                        const int p = d >> 1;
                        float cs = g_cos[l * 32 + p];
                        float sn = g_sin[l * 32 + p];
                        y0 = x0 * cs - x1 * sn;
                        y1 = x1 * cs + x0 * sn;
                    }
                    uint32_t off = (uint32_t)((((b * HH + hglob) * LL) + l) * 128 + d * 2);
                    uint32_t sw = off ^ ((off >> 3) & 0x70);
                    char* dst = (mode == 0) ? (char*)g_qh : (mode == 1) ? (char*)g_kh : (char*)g_vh;
                    *(uint32_t*)(dst + sw) = pack_h2(__float2half_rn(y0), __float2half_rn(y1));
                }
            }
        }
    }
}

// ---------------- QKV projection GEMM ----------------
__global__ void __launch_bounds__(256, 2) hmma_gemm_kernel(float* __restrict__ out, int mode0) {
    extern __shared__ __align__(1024) char smem[];
    gemm_body(smem_u32(smem), blockIdx.x & 7, mode0 + (blockIdx.x >> 3),
              blockIdx.y, blockIdx.z, out);
}

// ---------------- merged attention + out-projection (device-side dependency) ---------
// bid < 1024: attention (paired q-tiles). bid >= 1024: out-proj GEMM, spins on g_done.
__global__ void __launch_bounds__(256, 2) attn_out_kernel(float* __restrict__ out) {
    extern __shared__ __align__(1024) char smem[];
    const uint32_t sb = smem_u32(smem);
    const int bid = blockIdx.x;
    const int tid = threadIdx.x;

    if (bid >= 1024) {
        // ---- out-proj GEMM: wait for all attention CTAs ----
        if (tid == 0) {
            while (*(volatile int*)&g_done < 1024) { __nanosleep(256); }
        }
        __syncthreads();
        __threadfence();
        const int idx = bid - 1024;
        gemm_body(sb, idx & 7, 3, (idx >> 3) & 3, idx >> 5, out);
        return;
    }

    // ---- attention ----
    const int lane = tid & 31, w = tid >> 5;
    const int bx = bid & 1;
    const int qtA = 3 - bx, qtB = bx;
    const int bh = bid >> 1;
    const int b = bh >> 4, h = bh & 15;
    const int g = lane >> 2, tig = lane & 3;
    const float S2 = 0.125f * 1.44269504088896341f;

    const uint32_t QB = sb;
    const uint32_t FB = sb + 8;
    const uint32_t EB = sb + 24;
    const uint32_t QT = sb + 1024;
    const uint32_t KV = sb + 1024 + 32768;

    if (tid == 0) {
        MBAR_INIT(QB, 1);
        MBAR_INIT(FB, 1); MBAR_INIT(FB + 8, 1);
        MBAR_INIT(EB, 8); MBAR_INIT(EB + 8, 8);
    }
    __syncthreads();

    const size_t bh_off = (size_t)bh * LL * HDIM;
    const __half* kh = g_kh + bh_off;
    const __half* vh = g_vh + bh_off;

    const int n1 = 2 * qtA + 2, n2 = 2 * qtB + 2;
    const int ntot = n1 + n2;            // always 10

    auto issue = [&](int i) {
        int jt = (i < n1) ? i : (i - n1);
        int s = i & 1;
        uint32_t fb = FB + s * 8;
        uint32_t st = KV + s * 16384;
        MBAR_EXPECT_TX(fb, 16384);
        bulk_g2s(st,        kh + (size_t)jt * 4096, 8192, fb);
        bulk_g2s(st + 8192, vh + (size_t)jt * 4096, 8192, fb);
    };
    if (tid == 0) {
        MBAR_EXPECT_TX(QB, 32768);
        bulk_g2s(QT,         g_qh + bh_off + (size_t)qtA * 8192, 16384, QB);
        bulk_g2s(QT + 16384, g_qh + bh_off + (size_t)qtB * 8192, 16384, QB);
        issue(0);
        issue(1);
    }

    uint32_t swq[4];
    {
        uint32_t q0 = (uint32_t)(w * 16 + (lane & 15)) * 128 + (uint32_t)(lane >> 4) * 16;
        #pragma unroll
        for (int ks = 0; ks < 4; ks++) {
            uint32_t byt = q0 + (uint32_t)ks * 32;
            swq[ks] = byt ^ ((byt >> 3) & 0x70);
        }
    }

    float o[8][4];
    #pragma unroll
    for (int nf = 0; nf < 8; nf++)
        #pragma unroll
        for (int r = 0; r < 4; r++) o[nf][r] = 0.f;
    float m0 = -1e30f, m1 = -1e30f, l0 = 0.f, l1 = 0.f;

    mbar_wait(QB, 0);

    for (int i = 0; i < ntot; i++) {
        const int pass = (i >= n1);
        const int jt = pass ? (i - n1) : i;
        const int qt = pass ? qtB : qtA;
        const uint32_t qtile = QT + (pass ? 16384u : 0u);
        const int rowmin = qt * 128 + w * 16;

        const int s = i & 1;
        mbar_wait(FB + s * 8, (uint32_t)((i >> 1) & 1));
        const uint32_t kb = KV + s * 16384;

        if (jt * 64 <= rowmin + 15) {
            float p[8][4];
            #pragma unroll
            for (int nf = 0; nf < 8; nf++)
                #pragma unroll
                for (int r = 0; r < 4; r++) p[nf][r] = 0.f;

            #pragma unroll
            for (int ks = 0; ks < 4; ks++) {
                uint32_t ah[4];
                ldsm_x4(ah, qtile + swq[ks]);
                #pragma unroll
                for (int nfp = 0; nfp < 4; nfp++) {
                    uint32_t koff = (uint32_t)(nfp * 16 + (lane & 7) + ((lane & 16) >> 1)) * 128
                                    + (uint32_t)ks * 32 + ((lane & 8) << 1);
                    uint32_t swk = koff ^ ((koff >> 3) & 0x70);
                    uint32_t kf[4];
                    ldsm_x4(kf, kb + swk);
                    mma_f16(p[2 * nfp],     ah, &kf[0]);
                    mma_f16(p[2 * nfp + 1], ah, &kf[2]);
                }
            }

            const bool need_mask = (jt * 64 + 63) > rowmin;
            #pragma unroll
            for (int nf = 0; nf < 8; nf++)
                #pragma unroll
                for (int r = 0; r < 4; r++) {
                    float v = p[nf][r] * S2;
                    if (need_mask) {
                        int qr = rowmin + g + ((r & 2) << 2);
                        int kc = jt * 64 + 8 * nf + 2 * tig + (r & 1);
                        if (kc > qr) v = -1e30f;
                    }
                    p[nf][r] = v;
                }

            float mx0 = m0, mx1 = m1;
            #pragma unroll
            for (int nf = 0; nf < 8; nf++) {
                mx0 = fmaxf(mx0, fmaxf(p[nf][0], p[nf][1]));
                mx1 = fmaxf(mx1, fmaxf(p[nf][2], p[nf][3]));
            }
            mx0 = fmaxf(mx0, __shfl_xor_sync(0xffffffffu, mx0, 1));
            mx0 = fmaxf(mx0, __shfl_xor_sync(0xffffffffu, mx0, 2));
            mx1 = fmaxf(mx1, __shfl_xor_sync(0xffffffffu, mx1, 1));
            mx1 = fmaxf(mx1, __shfl_xor_sync(0xffffffffu, mx1, 2));
            float c0 = ex2(m0 - mx0), c1 = ex2(m1 - mx1);
            m0 = mx0; m1 = mx1;
            float s0 = 0.f, s1 = 0.f;
            #pragma unroll
            for (int nf = 0; nf < 8; nf++) {
                p[nf][0] = ex2(p[nf][0] - mx0); s0 += p[nf][0];
                p[nf][1] = ex2(p[nf][1] - mx0); s0 += p[nf][1];
                p[nf][2] = ex2(p[nf][2] - mx1); s1 += p[nf][2];
                p[nf][3] = ex2(p[nf][3] - mx1); s1 += p[nf][3];
            }
            s0 += __shfl_xor_sync(0xffffffffu, s0, 1);
            s0 += __shfl_xor_sync(0xffffffffu, s0, 2);
            s1 += __shfl_xor_sync(0xffffffffu, s1, 1);
            s1 += __shfl_xor_sync(0xffffffffu, s1, 2);
            l0 = l0 * c0 + s0;
            l1 = l1 * c1 + s1;
            #pragma unroll
            for (int nf = 0; nf < 8; nf++) {
                o[nf][0] *= c0; o[nf][1] *= c0;
                o[nf][2] *= c1; o[nf][3] *= c1;
            }

            #pragma unroll
            for (int j = 0; j < 4; j++) {
                uint32_t pah[4];
                #pragma unroll
                for (int half = 0; half < 2; half++) {
                    const float* pf = p[2 * j + half];
                    pah[2 * half]     = pack_h2(__float2half_rn(pf[0]), __float2half_rn(pf[1]));
                    pah[2 * half + 1] = pack_h2(__float2half_rn(pf[2]), __float2half_rn(pf[3]));
                }
                #pragma unroll
                for (int nfp = 0; nfp < 4; nfp++) {
                    uint32_t voff = (uint32_t)(16 * j + (lane & 7) + (lane & 8)) * 128
                                    + (uint32_t)nfp * 32 + (lane & 16);
                    uint32_t swv = voff ^ ((voff >> 3) & 0x70);
                    uint32_t vf[4];
                    ldsm_x4t(vf, kb + 8192 + swv);
                    mma_f16(o[2 * nfp],     pah, &vf[0]);
                    mma_f16(o[2 * nfp + 1], pah, &vf[2]);
                }
            }
        }
        if (lane == 0) MBAR_ARRIVE(EB + s * 8);
        if (tid == 0 && i + 2 < ntot) {
            mbar_wait(EB + s * 8, (uint32_t)((i >> 1) & 1));
            issue(i + 2);
        }

        if (i == n1 - 1 || i == ntot - 1) {
            const float i0 = 1.f / l0, i1 = 1.f / l1;
            const size_t tb = (((size_t)(b * 4 + qt) * 16) + h) * 16384;
            char* dh = (char*)g_xh + tb;
            #pragma unroll
            for (int nf = 0; nf < 8; nf++) {
                #pragma unroll
                for (int rh = 0; rh < 2; rh++) {
                    float y0 = o[nf][2 * rh]     * (rh ? i1 : i0);
                    float y1 = o[nf][2 * rh + 1] * (rh ? i1 : i0);
                    uint32_t off = (uint32_t)((w * 16 + g + 8 * rh) * 128 + (8 * nf + 2 * tig) * 2);
                    uint32_t sw = off ^ ((off >> 3) & 0x70);
                    *(uint32_t*)(dh + sw) = pack_h2(__float2half_rn(y0), __float2half_rn(y1));
                }
            }
            if (i == n1 - 1) {
                #pragma unroll
                for (int nf = 0; nf < 8; nf++)
                    #pragma unroll
                    for (int r = 0; r < 4; r++) o[nf][r] = 0.f;
                m0 = -1e30f; m1 = -1e30f; l0 = 0.f; l1 = 0.f;
            }
        }
    }

    // signal completion (stores visible to async + generic proxies at GPU scope)
    __syncthreads();
    asm volatile("fence.proxy.async;" ::: "memory");
    __threadfence();
    if (tid == 0) atomicAdd(&g_done, 1);
}

// ---------------- launch ----------------
extern "C" void kernel_launch(void* const* d_in, const int* in_sizes, int n_in,
                              void* d_out, int out_size) {
    const float* x  = (const float*)d_in[0];
    const float* qw = (const float*)d_in[1];
    const float* kw = (const float*)d_in[2];
    const float* vw = (const float*)d_in[3];
    const float* ow = (const float*)d_in[4];
    const float* rw = (const float*)d_in[5];
    const float* rb = (const float*)d_in[6];
    float* out = (float*)d_out;

    const int GEMM_SMEM = 1024 + 3 * 32768;           // 99328
    cudaFuncSetAttribute(hmma_gemm_kernel, cudaFuncAttributeMaxDynamicSharedMemorySize, GEMM_SMEM);
    cudaFuncSetAttribute(attn_out_kernel, cudaFuncAttributeMaxDynamicSharedMemorySize, GEMM_SMEM);

    int write_probs = (out_size >= BB * LL * DD + BB * EE) ? 1 : 0;

    convert_kernel<<<6184, 256>>>(x, qw, kw, vw, ow, rw, rb,
                                  out + (size_t)BB * LL * DD, write_probs);   // 0

    hmma_gemm_kernel<<<dim3(24, 4, BB), 256, GEMM_SMEM>>>(nullptr, 0);        // 1

    // attention (1024 blocks) + out-proj (1024 blocks) in one launch
    attn_out_kernel<<<2048, 256, GEMM_SMEM>>>(out);                           // 2
}

// round 17
// speedup vs baseline: 1.3022x; 1.2835x over previous
#include <cuda_runtime.h>
#include <cuda_bf16.h>
#include <cuda_fp16.h>
#include <cstdint>
#include <math.h>

#define BB 32
#define LL 512
#define DD 1024
#define HH 16
#define HDIM 64
#define EE 8

// ---------------- scratch (device globals; no allocation allowed) ----------------
__device__ float g_cos[LL * 32];
__device__ float g_sin[LL * 32];
__device__ int   g_routes[BB];
__device__ int   g_done;
__device__ int   g_rcnt[BB];
__device__ float g_part[BB][8][DD];

// X/AO tiles (single fp16): [rt(128)][kc(16)] each 128 rows x 64 cols (16KB), SW128
__device__ __half g_xh[(size_t)16384 * 1024];
// W^T tiles (single fp16): [mode(4)][e(8)][nt(8)][kc(16)] each 128(n) x 64(k), SW128
__device__ __half g_wt[(size_t)4 * 8 * 1024 * 1024];
// q/k/v single fp16: [B*H][512][64], SW128-swizzled 128B rows
__device__ __half g_qh[(size_t)BB * HH * LL * HDIM];
__device__ __half g_kh[(size_t)BB * HH * LL * HDIM];
__device__ __half g_vh[(size_t)BB * HH * LL * HDIM];

// ---------------- PTX helpers ----------------
__device__ __forceinline__ uint32_t smem_u32(const void* p) {
    uint32_t a;
    asm("{ .reg .u64 t; cvta.to.shared.u64 t, %1; cvt.u32.u64 %0, t; }" : "=r"(a) : "l"(p));
    return a;
}

#define MBAR_INIT(a, n) \
    asm volatile("mbarrier.init.shared.b64 [%0], %1;" :: "r"(a), "r"((uint32_t)(n)) : "memory")
#define MBAR_EXPECT_TX(a, b) \
    asm volatile("mbarrier.arrive.expect_tx.shared.b64 _, [%0], %1;" :: "r"(a), "r"((uint32_t)(b)) : "memory")
#define MBAR_ARRIVE(a) \
    asm volatile("mbarrier.arrive.shared.b64 _, [%0];" :: "r"(a) : "memory")

__device__ __forceinline__ void mbar_wait(uint32_t mbar, uint32_t parity) {
    asm volatile(
        "{\n\t.reg .pred P;\n\t"
        "WL_%=:\n\t"
        "mbarrier.try_wait.parity.acquire.cta.shared::cta.b64 P, [%0], %1, 0x989680;\n\t"
        "@P bra.uni WD_%=;\n\t"
        "bra.uni WL_%=;\n\t"
        "WD_%=:\n\t}"
        :: "r"(mbar), "r"(parity) : "memory");
}

__device__ __forceinline__ void bulk_g2s(uint32_t dst, const void* src, uint32_t bytes, uint32_t mbar) {
    asm volatile(
        "cp.async.bulk.shared::cluster.global.mbarrier::complete_tx::bytes [%0], [%1], %2, [%3];"
        :: "r"(dst), "l"(src), "r"(bytes), "r"(mbar) : "memory");
}

__device__ __forceinline__ void ldsm_x4(uint32_t* r, uint32_t a) {
    asm volatile("ldmatrix.sync.aligned.m8n8.x4.shared.b16 {%0,%1,%2,%3}, [%4];"
                 : "=r"(r[0]), "=r"(r[1]), "=r"(r[2]), "=r"(r[3]) : "r"(a));
}
__device__ __forceinline__ void ldsm_x4t(uint32_t* r, uint32_t a) {
    asm volatile("ldmatrix.sync.aligned.m8n8.x4.trans.shared.b16 {%0,%1,%2,%3}, [%4];"
                 : "=r"(r[0]), "=r"(r[1]), "=r"(r[2]), "=r"(r[3]) : "r"(a));
}
__device__ __forceinline__ void mma_f16(float* d, const uint32_t* a, const uint32_t* b) {
    asm volatile(
        "mma.sync.aligned.m16n8k16.row.col.f32.f16.f16.f32 "
        "{%0,%1,%2,%3}, {%4,%5,%6,%7}, {%8,%9}, {%0,%1,%2,%3};"
        : "+f"(d[0]), "+f"(d[1]), "+f"(d[2]), "+f"(d[3])
        : "r"(a[0]), "r"(a[1]), "r"(a[2]), "r"(a[3]), "r"(b[0]), "r"(b[1]));
}
__device__ __forceinline__ float ex2(float x) {
    float r;
    asm("ex2.approx.f32 %0, %1;" : "=f"(r) : "f"(x));
    return r;
}

__device__ __forceinline__ uint32_t pack_h2(__half a, __half b) {
    return (uint32_t)__half_as_ushort(a) | ((uint32_t)__half_as_ushort(b) << 16);
}

// ---------------- merged convert: router(2-phase) + rope + X tiles + W^T tiles -------
__global__ void convert_kernel(const float* __restrict__ x,
                               const float* __restrict__ qw, const float* __restrict__ kw,
                               const float* __restrict__ vw, const float* __restrict__ ow,
                               const float* __restrict__ rw, const float* __restrict__ rb,
                               float* __restrict__ probs_out, int write_probs) {
    __shared__ float sm[64][129];
    const int bid = blockIdx.x;
    const int tid = threadIdx.x;

    if (bid < 256) {
        // ---- router phase 1: partial sums (8 blocks per batch, 64 rows each) ----
        const int b = bid >> 3, p = bid & 7;
        float acc[4] = {0.f, 0.f, 0.f, 0.f};
        const float* xp = x + ((size_t)b * LL + p * 64) * DD;
        for (int l = 0; l < 64; l++) {
            #pragma unroll
            for (int q = 0; q < 4; q++)
                acc[q] += xp[(size_t)l * DD + tid + q * 256];
        }
        #pragma unroll
        for (int q = 0; q < 4; q++) g_part[b][p][tid + q * 256] = acc[q];
        __syncthreads();
        __threadfence();

        __shared__ int lastf;
        if (tid == 0) lastf = (atomicAdd(&g_rcnt[b], 1) == 7);
        __syncthreads();
        if (!lastf) return;
        __threadfence();

        // ---- router phase 2 (last block): mean -> logits -> softmax/argmax ----
        float* mean = &sm[0][0];
        float* logits = &sm[33][0];
        #pragma unroll
        for (int q = 0; q < 4; q++) {
            const int d = tid + q * 256;
            float s = 0.f;
            #pragma unroll
            for (int pp = 0; pp < 8; pp++) s += g_part[b][pp][d];   // fixed order
            mean[d] = s * (1.0f / (float)LL);
        }
        __syncthreads();

        int w = tid >> 5;
        int lane = tid & 31;
        if (w < EE) {
            float s = 0.f;
            for (int d = lane; d < DD; d += 32) s += mean[d] * rw[d * EE + w];
            #pragma unroll
            for (int o = 16; o > 0; o >>= 1) s += __shfl_down_sync(0xffffffffu, s, o);
            if (lane == 0) logits[w] = s + rb[w];
        }
        __syncthreads();

        if (tid == 0) {
            float m = logits[0]; int arg = 0;
            #pragma unroll
            for (int e = 1; e < EE; e++) if (logits[e] > m) { m = logits[e]; arg = e; }
            float pr[EE], sum = 0.f;
            #pragma unroll
            for (int e = 0; e < EE; e++) { pr[e] = expf(logits[e] - m); sum += pr[e]; }
            if (write_probs) {
                float inv = 1.0f / sum;
                #pragma unroll
                for (int e = 0; e < EE; e++) probs_out[b * EE + e] = pr[e] * inv;
            }
            g_routes[b] = arg;
            g_rcnt[b] = 0;                     // reset for graph replay
        }
        return;
    }

    if (bid < 264) {
        // ---- rope tables (+ dependency counter reset) ----
        if (bid == 256 && tid == 0) g_done = 0;
        int base = (bid - 256) * 2048 + tid * 8;
        #pragma unroll
        for (int j = 0; j < 8; j++) {
            int idx = base + j;
            int l = idx >> 5;
            int jp = idx & 31;
            float inv = 1.0f / powf(10000.0f, (float)(2 * jp) / 64.0f);
            float ang = (float)l * inv;
            g_cos[idx] = cosf(ang);
            g_sin[idx] = sinf(ang);
        }
        return;
    }

    if (bid < 2312) {
        const int bx = bid - 264;
        const int rt = bx >> 4, kc = bx & 15;
        const size_t tb = ((size_t)rt * 16 + kc) * 8192;
        char* dh = (char*)(g_xh + tb);
        #pragma unroll
        for (int i = 0; i < 4; i++) {
            int u = tid + i * 256;
            int r = u >> 3, k8 = u & 7;
            const float* p = x + ((size_t)(rt * 128 + r)) * DD + kc * 64 + k8 * 8;
            float4 a = *(const float4*)p;
            float4 b4 = *(const float4*)(p + 4);
            uint32_t off = (uint32_t)(u * 16);
            off ^= (off >> 3) & 0x70;
            *(uint4*)(dh + off) = make_uint4(
                pack_h2(__float2half_rn(a.x),  __float2half_rn(a.y)),
                pack_h2(__float2half_rn(a.z),  __float2half_rn(a.w)),
                pack_h2(__float2half_rn(b4.x), __float2half_rn(b4.y)),
                pack_h2(__float2half_rn(b4.z), __float2half_rn(b4.w)));
        }
    } else {
        const int idx = bid - 2312;
        const int kc = idx & 15, nt = (idx >> 4) & 7;
        const int e = (idx >> 7) & 7, mode = idx >> 10;
        const float* W = (mode == 0) ? qw : (mode == 1) ? kw : (mode == 2) ? vw : ow;
        const float* src = W + ((size_t)e * DD + kc * 64) * DD + nt * 128;

        #pragma unroll
        for (int i = 0; i < 8; i++) {
            int idx2 = tid + i * 256;
            int kr = idx2 >> 5, nc = (idx2 & 31) << 2;
            float4 v = *(const float4*)(src + (size_t)kr * DD + nc);
            sm[kr][nc] = v.x; sm[kr][nc + 1] = v.y; sm[kr][nc + 2] = v.z; sm[kr][nc + 3] = v.w;
        }
        __syncthreads();

        const size_t tb = (((size_t)(mode * 8 + e) * 8 + nt) * 16 + kc) * 8192;
        char* dw = (char*)(g_wt + tb);
        #pragma unroll
        for (int i = 0; i < 4; i++) {
            int u = tid + i * 256;
            int n = u >> 3, k8 = u & 7;
            __half h[8];
            #pragma unroll
            for (int j = 0; j < 8; j++) h[j] = __float2half_rn(sm[k8 * 8 + j][n]);
            uint32_t off = (uint32_t)(u * 16);
            off ^= (off >> 3) & 0x70;
            *(uint4*)(dw + off) = make_uint4(pack_h2(h[0], h[1]), pack_h2(h[2], h[3]),
                                             pack_h2(h[4], h[5]), pack_h2(h[6], h[7]));
        }
    }
}

// ---------------- GEMM body (CTA 128x128, warp 64x32, 3-stage pipeline) --------------
__device__ __forceinline__ void gemm_body(uint32_t sb, int nt, int mode, int mt, int b,
                                          float* __restrict__ out) {
    const int tid = threadIdx.x;
    const int lane = tid & 31, wid = tid >> 5;
    const int wm = wid >> 2, wn = wid & 3;
    const int e = g_routes[b];

    const uint32_t FULLB = sb;
    const uint32_t EMPTB = sb + 24;
    const uint32_t TILES = sb + 1024;

    if (tid == 0) {
        #pragma unroll
        for (int s = 0; s < 3; s++) { MBAR_INIT(FULLB + s * 8, 1); MBAR_INIT(EMPTB + s * 8, 8); }
    }
    __syncthreads();

    const __half* Ah = g_xh + ((size_t)(b * 4 + mt) * 16) * 8192;
    const __half* B0 = g_wt + (((size_t)(mode * 8 + e) * 8 + nt) * 16) * 8192;

    auto issue = [&](int c) {
        int s = c % 3;
        uint32_t fb = FULLB + s * 8;
        uint32_t st = TILES + s * 32768;
        MBAR_EXPECT_TX(fb, 32768);
        bulk_g2s(st,         Ah + (size_t)c * 8192, 16384, fb);
        bulk_g2s(st + 16384, B0 + (size_t)c * 8192, 16384, fb);
    };
    if (tid == 0) { issue(0); issue(1); issue(2); }

    float acc[4][4][4];
    #pragma unroll
    for (int mf = 0; mf < 4; mf++)
        #pragma unroll
        for (int nf = 0; nf < 4; nf++)
            #pragma unroll
            for (int r = 0; r < 4; r++) acc[mf][nf][r] = 0.f;

    const uint32_t a_row  = (uint32_t)(wm * 64 + (lane & 15)) * 128;
    const uint32_t a_koff = (uint32_t)(lane >> 4) * 16;
    const uint32_t b_row  = (uint32_t)(wn * 32 + (lane & 7) + ((lane >> 4) << 3)) * 128;
    const uint32_t b_koff = (uint32_t)((lane >> 3) & 1) * 16;

    for (int c = 0; c < 16; c++) {
        const int s = c % 3;
        const uint32_t phase = (uint32_t)((c / 3) & 1);
        mbar_wait(FULLB + s * 8, phase);
        const uint32_t base = TILES + s * 32768;

        #pragma unroll
        for (int ks = 0; ks < 4; ks++) {
            const uint32_t k0b = (uint32_t)ks * 32;
            uint32_t ah[4][4];
            #pragma unroll
            for (int mf = 0; mf < 4; mf++) {
                uint32_t byt = a_row + (uint32_t)mf * 2048 + a_koff + k0b;
                uint32_t sw = byt ^ ((byt >> 3) & 0x70);
                ldsm_x4(ah[mf], base + sw);
            }
            uint32_t bf[2][4];
            #pragma unroll
            for (int p = 0; p < 2; p++) {
                uint32_t byt = b_row + (uint32_t)p * 2048 + b_koff + k0b;
                uint32_t sw = byt ^ ((byt >> 3) & 0x70);
                ldsm_x4(bf[p], base + 16384 + sw);
            }
            if (ks == 3 && lane == 0) MBAR_ARRIVE(EMPTB + s * 8);

            #pragma unroll
            for (int p = 0; p < 2; p++)
                #pragma unroll
                for (int mf = 0; mf < 4; mf++) {
                    mma_f16(acc[mf][2 * p],     ah[mf], &bf[p][0]);
                    mma_f16(acc[mf][2 * p + 1], ah[mf], &bf[p][2]);
                }
        }
        if (tid == 0 && c + 3 < 16) {
            mbar_wait(EMPTB + s * 8, phase);
            issue(c + 3);
        }
    }

    const int l_base = mt * 128 + wm * 64 + (lane >> 2);
    const int tig = lane & 3;
    const int colbase = nt * 128 + wn * 32;
    const int hglob = colbase >> 6;
    const int d0 = colbase & 63;

    #pragma unroll
    for (int mf = 0; mf < 4; mf++) {
        #pragma unroll
        for (int rh = 0; rh < 2; rh++) {
            const int l = l_base + mf * 16 + 8 * rh;
            #pragma unroll
            for (int nf = 0; nf < 4; nf++) {
                const int d = d0 + 8 * nf + 2 * tig;
                float x0 = acc[mf][nf][2 * rh];
                float x1 = acc[mf][nf][2 * rh + 1];
                if (mode == 3) {
                    float2* dst = (float2*)(out + ((size_t)b * LL + l) * DD + hglob * 64 + d);
                    *dst = make_float2(x0, x1);
                } else {
                    float y0, y1;
                    if (mode == 2) { y0 = x0; y1 = x1; }
                    else {
                        const int p = d >> 1;
                        float cs = g_cos[l * 32 + p];
                        float sn = g_sin[l * 32 + p];
                        y0 = x0 * cs - x1 * sn;
                        y1 = x1 * cs + x0 * sn;
                    }
                    uint32_t off = (uint32_t)((((b * HH + hglob) * LL) + l) * 128 + d * 2);
                    uint32_t sw = off ^ ((off >> 3) & 0x70);
                    char* dst = (mode == 0) ? (char*)g_qh : (mode == 1) ? (char*)g_kh : (char*)g_vh;
                    *(uint32_t*)(dst + sw) = pack_h2(__float2half_rn(y0), __float2half_rn(y1));
                }
            }
        }
    }
}

// ---------------- QKV projection GEMM ----------------
__global__ void __launch_bounds__(256, 2) hmma_gemm_kernel(float* __restrict__ out, int mode0) {
    extern __shared__ __align__(1024) char smem[];
    gemm_body(smem_u32(smem), blockIdx.x & 7, mode0 + (blockIdx.x >> 3),
              blockIdx.y, blockIdx.z, out);
}

// ---------------- merged attention + out-projection (device-side dependency) ---------
__global__ void __launch_bounds__(256, 2) attn_out_kernel(float* __restrict__ out) {
    extern __shared__ __align__(1024) char smem[];
    const uint32_t sb = smem_u32(smem);
    const int bid = blockIdx.x;
    const int tid = threadIdx.x;

    if (bid >= 1024) {
        if (tid == 0) {
            while (*(volatile int*)&g_done < 1024) { __nanosleep(256); }
        }
        __syncthreads();
        __threadfence();
        const int idx = bid - 1024;
        gemm_body(sb, idx & 7, 3, (idx >> 3) & 3, idx >> 5, out);
        return;
    }

    // ---- attention ----
    const int lane = tid & 31, w = tid >> 5;
    const int bx = bid & 1;
    const int qtA = 3 - bx, qtB = bx;
    const int bh = bid >> 1;
    const int b = bh >> 4, h = bh & 15;
    const int g = lane >> 2, tig = lane & 3;
    const float S2 = 0.125f * 1.44269504088896341f;

    const uint32_t QB = sb;
    const uint32_t FB = sb + 8;
    const uint32_t EB = sb + 24;
    const uint32_t QT = sb + 1024;
    const uint32_t KV = sb + 1024 + 32768;

    if (tid == 0) {
        MBAR_INIT(QB, 1);
        MBAR_INIT(FB, 1); MBAR_INIT(FB + 8, 1);
        MBAR_INIT(EB, 8); MBAR_INIT(EB + 8, 8);
    }
    __syncthreads();

    const size_t bh_off = (size_t)bh * LL * HDIM;
    const __half* kh = g_kh + bh_off;
    const __half* vh = g_vh + bh_off;

    const int n1 = 2 * qtA + 2, n2 = 2 * qtB + 2;
    const int ntot = n1 + n2;            // always 10

    auto issue = [&](int i) {
        int jt = (i < n1) ? i : (i - n1);
        int s = i & 1;
        uint32_t fb = FB + s * 8;
        uint32_t st = KV + s * 16384;
        MBAR_EXPECT_TX(fb, 16384);
        bulk_g2s(st,        kh + (size_t)jt * 4096, 8192, fb);
        bulk_g2s(st + 8192, vh + (size_t)jt * 4096, 8192, fb);
    };
    if (tid == 0) {
        MBAR_EXPECT_TX(QB, 32768);
        bulk_g2s(QT,         g_qh + bh_off + (size_t)qtA * 8192, 16384, QB);
        bulk_g2s(QT + 16384, g_qh + bh_off + (size_t)qtB * 8192, 16384, QB);
        issue(0);
        issue(1);
    }

    uint32_t swq[4];
    {
        uint32_t q0 = (uint32_t)(w * 16 + (lane & 15)) * 128 + (uint32_t)(lane >> 4) * 16;
        #pragma unroll
        for (int ks = 0; ks < 4; ks++) {
            uint32_t byt = q0 + (uint32_t)ks * 32;
            swq[ks] = byt ^ ((byt >> 3) & 0x70);
        }
    }

    float o[8][4];
    #pragma unroll
    for (int nf = 0; nf < 8; nf++)
        #pragma unroll
        for (int r = 0; r < 4; r++) o[nf][r] = 0.f;
    float m0 = -1e30f, m1 = -1e30f, l0 = 0.f, l1 = 0.f;

    mbar_wait(QB, 0);

    for (int i = 0; i < ntot; i++) {
        const int pass = (i >= n1);
        const int jt = pass ? (i - n1) : i;
        const int qt = pass ? qtB : qtA;
        const uint32_t qtile = QT + (pass ? 16384u : 0u);
        const int rowmin = qt * 128 + w * 16;

        const int s = i & 1;
        mbar_wait(FB + s * 8, (uint32_t)((i >> 1) & 1));
        const uint32_t kb = KV + s * 16384;

        if (jt * 64 <= rowmin + 15) {
            float p[8][4];
            #pragma unroll
            for (int nf = 0; nf < 8; nf++)
                #pragma unroll
                for (int r = 0; r < 4; r++) p[nf][r] = 0.f;

            #pragma unroll
            for (int ks = 0; ks < 4; ks++) {
                uint32_t ah[4];
                ldsm_x4(ah, qtile + swq[ks]);
                #pragma unroll
                for (int nfp = 0; nfp < 4; nfp++) {
                    uint32_t koff = (uint32_t)(nfp * 16 + (lane & 7) + ((lane & 16) >> 1)) * 128
                                    + (uint32_t)ks * 32 + ((lane & 8) << 1);
                    uint32_t swk = koff ^ ((koff >> 3) & 0x70);
                    uint32_t kf[4];
                    ldsm_x4(kf, kb + swk);
                    mma_f16(p[2 * nfp],     ah, &kf[0]);
                    mma_f16(p[2 * nfp + 1], ah, &kf[2]);
                }
            }

            const bool need_mask = (jt * 64 + 63) > rowmin;
            #pragma unroll
            for (int nf = 0; nf < 8; nf++)
                #pragma unroll
                for (int r = 0; r < 4; r++) {
                    float v = p[nf][r] * S2;
                    if (need_mask) {
                        int qr = rowmin + g + ((r & 2) << 2);
                        int kc = jt * 64 + 8 * nf + 2 * tig + (r & 1);
                        if (kc > qr) v = -1e30f;
                    }
                    p[nf][r] = v;
                }

            float mx0 = m0, mx1 = m1;
            #pragma unroll
            for (int nf = 0; nf < 8; nf++) {
                mx0 = fmaxf(mx0, fmaxf(p[nf][0], p[nf][1]));
                mx1 = fmaxf(mx1, fmaxf(p[nf][2], p[nf][3]));
            }
            mx0 = fmaxf(mx0, __shfl_xor_sync(0xffffffffu, mx0, 1));
            mx0 = fmaxf(mx0, __shfl_xor_sync(0xffffffffu, mx0, 2));
            mx1 = fmaxf(mx1, __shfl_xor_sync(0xffffffffu, mx1, 1));
            mx1 = fmaxf(mx1, __shfl_xor_sync(0xffffffffu, mx1, 2));
            float c0 = ex2(m0 - mx0), c1 = ex2(m1 - mx1);
            m0 = mx0; m1 = mx1;
            float s0 = 0.f, s1 = 0.f;
            #pragma unroll
            for (int nf = 0; nf < 8; nf++) {
                p[nf][0] = ex2(p[nf][0] - mx0); s0 += p[nf][0];
                p[nf][1] = ex2(p[nf][1] - mx0); s0 += p[nf][1];
                p[nf][2] = ex2(p[nf][2] - mx1); s1 += p[nf][2];
                p[nf][3] = ex2(p[nf][3] - mx1); s1 += p[nf][3];
            }
            s0 += __shfl_xor_sync(0xffffffffu, s0, 1);
            s0 += __shfl_xor_sync(0xffffffffu, s0, 2);
            s1 += __shfl_xor_sync(0xffffffffu, s1, 1);
            s1 += __shfl_xor_sync(0xffffffffu, s1, 2);
            l0 = l0 * c0 + s0;
            l1 = l1 * c1 + s1;
            #pragma unroll
            for (int nf = 0; nf < 8; nf++) {
                o[nf][0] *= c0; o[nf][1] *= c0;
                o[nf][2] *= c1; o[nf][3] *= c1;
            }

            #pragma unroll
            for (int j = 0; j < 4; j++) {
                uint32_t pah[4];
                #pragma unroll
                for (int half = 0; half < 2; half++) {
                    const float* pf = p[2 * j + half];
                    pah[2 * half]     = pack_h2(__float2half_rn(pf[0]), __float2half_rn(pf[1]));
                    pah[2 * half + 1] = pack_h2(__float2half_rn(pf[2]), __float2half_rn(pf[3]));
                }
                #pragma unroll
                for (int nfp = 0; nfp < 4; nfp++) {
                    uint32_t voff = (uint32_t)(16 * j + (lane & 7) + (lane & 8)) * 128
                                    + (uint32_t)nfp * 32 + (lane & 16);
                    uint32_t swv = voff ^ ((voff >> 3) & 0x70);
                    uint32_t vf[4];
                    ldsm_x4t(vf, kb + 8192 + swv);
                    mma_f16(o[2 * nfp],     pah, &vf[0]);
                    mma_f16(o[2 * nfp + 1], pah, &vf[2]);
                }
            }
        }
        if (lane == 0) MBAR_ARRIVE(EB + s * 8);
        if (tid == 0 && i + 2 < ntot) {
            mbar_wait(EB + s * 8, (uint32_t)((i >> 1) & 1));
            issue(i + 2);
        }

        if (i == n1 - 1 || i == ntot - 1) {
            const float i0 = 1.f / l0, i1 = 1.f / l1;
            const size_t tb = (((size_t)(b * 4 + qt) * 16) + h) * 16384;
            char* dh = (char*)g_xh + tb;
            #pragma unroll
            for (int nf = 0; nf < 8; nf++) {
                #pragma unroll
                for (int rh = 0; rh < 2; rh++) {
                    float y0 = o[nf][2 * rh]     * (rh ? i1 : i0);
                    float y1 = o[nf][2 * rh + 1] * (rh ? i1 : i0);
                    uint32_t off = (uint32_t)((w * 16 + g + 8 * rh) * 128 + (8 * nf + 2 * tig) * 2);
                    uint32_t sw = off ^ ((off >> 3) & 0x70);
                    *(uint32_t*)(dh + sw) = pack_h2(__float2half_rn(y0), __float2half_rn(y1));
                }
            }
            if (i == n1 - 1) {
                #pragma unroll
                for (int nf = 0; nf < 8; nf++)
                    #pragma unroll
                    for (int r = 0; r < 4; r++) o[nf][r] = 0.f;
                m0 = -1e30f; m1 = -1e30f; l0 = 0.f; l1 = 0.f;
            }
        }
    }

    __syncthreads();
    asm volatile("fence.proxy.async;" ::: "memory");
    __threadfence();
    if (tid == 0) atomicAdd(&g_done, 1);
}

// ---------------- launch ----------------
extern "C" void kernel_launch(void* const* d_in, const int* in_sizes, int n_in,
                              void* d_out, int out_size) {
    const float* x  = (const float*)d_in[0];
    const float* qw = (const float*)d_in[1];
    const float* kw = (const float*)d_in[2];
    const float* vw = (const float*)d_in[3];
    const float* ow = (const float*)d_in[4];
    const float* rw = (const float*)d_in[5];
    const float* rb = (const float*)d_in[6];
    float* out = (float*)d_out;

    const int GEMM_SMEM = 1024 + 3 * 32768;           // 99328
    cudaFuncSetAttribute(hmma_gemm_kernel, cudaFuncAttributeMaxDynamicSharedMemorySize, GEMM_SMEM);
    cudaFuncSetAttribute(attn_out_kernel, cudaFuncAttributeMaxDynamicSharedMemorySize, GEMM_SMEM);

    int write_probs = (out_size >= BB * LL * DD + BB * EE) ? 1 : 0;

    convert_kernel<<<6408, 256>>>(x, qw, kw, vw, ow, rw, rb,
                                  out + (size_t)BB * LL * DD, write_probs);   // 0

    hmma_gemm_kernel<<<dim3(24, 4, BB), 256, GEMM_SMEM>>>(nullptr, 0);        // 1

    attn_out_kernel<<<2048, 256, GEMM_SMEM>>>(out);                           // 2
}